// round 3
// baseline (speedup 1.0000x reference)
#include <cuda_runtime.h>

#define C16  16
#define GH32 32
#define W512 512
#define HW   (512 * 512)

// Packed f32x2 FMA (Blackwell sm_103a) — 2 fp32 FMAs per instruction.
__device__ __forceinline__ float2 ffma2(float2 a, float2 b, float2 c) {
    float2 d;
    asm("fma.rn.f32x2 %0, %1, %2, %3;"
        : "=l"(reinterpret_cast<unsigned long long&>(d))
        : "l"(reinterpret_cast<unsigned long long&>(a)),
          "l"(reinterpret_cast<unsigned long long&>(b)),
          "l"(reinterpret_cast<unsigned long long&>(c)));
    return d;
}

// Identity: softmax over 8 identical affinities = 1/8 each, so
//   s      = mean of 8 rolls of x
//   agg    = mw @ s + mb
//   hidden = relu(W1 @ x + W2 @ s + b1'),  W2 = g1w[:,16:] @ mw,
//            b1' = g1b + g1w[:,16:] @ mb   (folded per-block)
//   out    = agg * sigmoid(g2w @ hidden + g2b)
//
// One thread = 2 horizontally-adjacent pixels as ONE packed f32x2 lane.
// __launch_bounds__(256, 2) caps regs at 128 -> 16 warps/SM (vs 8 before):
// the round-2 profile showed a latency-bound kernel (issue 32%, occ 12.4%).
__global__ __launch_bounds__(256, 2) void fused_graphaug_kernel(
    const float* __restrict__ x,
    const float* __restrict__ mw,  const float* __restrict__ mb,
    const float* __restrict__ g1w, const float* __restrict__ g1b,
    const float* __restrict__ g2w, const float* __restrict__ g2b,
    float* __restrict__ out)
{
    // Weights as duplicated pairs (w,w): one LDS.128 (broadcast, conflict-free)
    // yields two ready f32x2 operands.
    __shared__ __align__(16) float smwD[C16 * C16 * 2];   // [d][c] = mw[d][c]
    __shared__ __align__(16) float sW1T[C16 * GH32 * 2];  // [c][j] = g1w[j][c]
    __shared__ __align__(16) float sW2T[C16 * GH32 * 2];  // [c][j] = (g1w[:,16:] @ mw)[j][c]
    __shared__ __align__(16) float sg2T[GH32 * C16 * 2];  // [j][g] = g2w[g][j]
    __shared__ __align__(16) float smbp[C16 * 2];
    __shared__ __align__(16) float sb1p[GH32 * 2];
    __shared__ __align__(16) float sgbp[C16 * 2];

    const int t = threadIdx.x;

    // ---- Stage weights (tiny; inputs L2-resident) ----
    for (int i = t; i < C16 * C16; i += 256) {
        int d = i >> 4, c = i & 15;
        float v = mw[d * C16 + c];
        smwD[i * 2] = v; smwD[i * 2 + 1] = v;
    }
    for (int i = t; i < C16 * GH32; i += 256) {
        int c = i >> 5, j = i & 31;
        float v = g1w[j * (2 * C16) + c];
        sW1T[i * 2] = v; sW1T[i * 2 + 1] = v;
        float acc = 0.f;
        #pragma unroll
        for (int k = 0; k < C16; k++)
            acc += g1w[j * (2 * C16) + C16 + k] * mw[k * C16 + c];
        sW2T[i * 2] = acc; sW2T[i * 2 + 1] = acc;
    }
    for (int i = t; i < GH32 * C16; i += 256) {
        int j = i >> 4, g = i & 15;
        float v = g2w[g * GH32 + j];
        sg2T[i * 2] = v; sg2T[i * 2 + 1] = v;
    }
    if (t < C16) {
        float v = mb[t];  smbp[2 * t] = v; smbp[2 * t + 1] = v;
        float u = g2b[t]; sgbp[2 * t] = u; sgbp[2 * t + 1] = u;
    }
    if (t >= 32 && t < 32 + GH32) {
        int j = t - 32;
        float acc = g1b[j];
        #pragma unroll
        for (int k = 0; k < C16; k++)
            acc += g1w[j * (2 * C16) + C16 + k] * mb[k];
        sb1p[2 * j] = acc; sb1p[2 * j + 1] = acc;
    }
    __syncthreads();

    // ---- Pixel-pair indexing (524288 pairs, 2048 blocks x 256 threads) ----
    const int pair = blockIdx.x * 256 + t;
    const int p0   = pair * 2;                  // even pixel index
    const int w0   = p0 & (W512 - 1);           // even column
    const int h    = (p0 >> 9) & (W512 - 1);
    const int b    = p0 >> 18;

    const float* xb    = x + (size_t)b * C16 * HW;
    const int    center = h * W512 + w0;

    // Fixed offsets (dy,dx); source = ((h-dy)&511, (w-dx)&511)
    constexpr int DY[8] = {-4, -4, -4, -3, -2, 2, 3, 4};
    constexpr int DX[8] = {-4, -1,  2,  4, -3, 3, -2, 4};
    int roff[8], cb[8];
    #pragma unroll
    for (int i = 0; i < 8; i++) {
        roff[i] = ((h - DY[i]) & (W512 - 1)) * W512;
        cb[i]   = (w0 - DX[i]) & (W512 - 1);
    }

    // ---- s = mean of 8 rolls per channel (one f32x2 lane) ----
    float2 sv[C16];
    #pragma unroll
    for (int c = 0; c < C16; c++) {
        const float* xp = xb + c * HW;
        float a0 = 0.f, a1 = 0.f;
        #pragma unroll
        for (int i = 0; i < 8; i++) {
            if ((DX[i] & 1) == 0) {
                // even dx: cb even <= 510 -> aligned contiguous float2
                float2 v = *reinterpret_cast<const float2*>(xp + roff[i] + cb[i]);
                a0 += v.x; a1 += v.y;
            } else {
                a0 += __ldg(xp + roff[i] + cb[i]);
                a1 += __ldg(xp + roff[i] + ((cb[i] + 1) & (W512 - 1)));
            }
        }
        sv[c] = make_float2(a0 * 0.125f, a1 * 0.125f);
    }

    // ---- gate accumulators ----
    float2 gacc[C16];
    #pragma unroll
    for (int g = 0; g < C16; g++)
        gacc[g] = *reinterpret_cast<const float2*>(&sgbp[2 * g]);

    // ---- hidden in 4 chunks of 8 units ----
    #pragma unroll
    for (int jt = 0; jt < 4; jt++) {
        const int jb = jt * 8;
        float2 hreg[8];
        #pragma unroll
        for (int jj = 0; jj < 8; jj++)
            hreg[jj] = *reinterpret_cast<const float2*>(&sb1p[2 * (jb + jj)]);

        // W1 @ x (center x re-loaded per chunk: L1-resident; saves 32 regs)
        #pragma unroll
        for (int c = 0; c < C16; c++) {
            float2 xc = *reinterpret_cast<const float2*>(xb + c * HW + center);
            #pragma unroll
            for (int jj = 0; jj < 8; jj += 2) {
                float4 wq = *reinterpret_cast<const float4*>(&sW1T[(c * GH32 + jb + jj) * 2]);
                hreg[jj]     = ffma2(make_float2(wq.x, wq.y), xc, hreg[jj]);
                hreg[jj + 1] = ffma2(make_float2(wq.z, wq.w), xc, hreg[jj + 1]);
            }
        }
        // W2 @ s
        #pragma unroll
        for (int c = 0; c < C16; c++) {
            float2 sc = sv[c];
            #pragma unroll
            for (int jj = 0; jj < 8; jj += 2) {
                float4 wq = *reinterpret_cast<const float4*>(&sW2T[(c * GH32 + jb + jj) * 2]);
                hreg[jj]     = ffma2(make_float2(wq.x, wq.y), sc, hreg[jj]);
                hreg[jj + 1] = ffma2(make_float2(wq.z, wq.w), sc, hreg[jj + 1]);
            }
        }
        // relu
        #pragma unroll
        for (int jj = 0; jj < 8; jj++) {
            hreg[jj].x = fmaxf(hreg[jj].x, 0.f);
            hreg[jj].y = fmaxf(hreg[jj].y, 0.f);
        }
        // gate pre-activation: gacc += g2w[:, j] * h_j
        #pragma unroll
        for (int jj = 0; jj < 8; jj++) {
            float2 hv = hreg[jj];
            const int j = jb + jj;
            #pragma unroll
            for (int g = 0; g < C16; g += 2) {
                float4 wq = *reinterpret_cast<const float4*>(&sg2T[(j * C16 + g) * 2]);
                gacc[g]     = ffma2(make_float2(wq.x, wq.y), hv, gacc[g]);
                gacc[g + 1] = ffma2(make_float2(wq.z, wq.w), hv, gacc[g + 1]);
            }
        }
    }

    // ---- stream agg per output channel, gate + store ----
    float* ob = out + (size_t)b * C16 * HW + center;
    #pragma unroll
    for (int d = 0; d < C16; d++) {
        float2 ag = *reinterpret_cast<const float2*>(&smbp[2 * d]);
        #pragma unroll
        for (int c = 0; c < C16; c += 2) {
            float4 wq = *reinterpret_cast<const float4*>(&smwD[(d * C16 + c) * 2]);
            ag = ffma2(make_float2(wq.x, wq.y), sv[c],     ag);
            ag = ffma2(make_float2(wq.z, wq.w), sv[c + 1], ag);
        }
        float gx = 1.f / (1.f + __expf(-gacc[d].x));
        float gy = 1.f / (1.f + __expf(-gacc[d].y));
        *reinterpret_cast<float2*>(ob + (size_t)d * HW) =
            make_float2(ag.x * gx, ag.y * gy);
    }
}

extern "C" void kernel_launch(void* const* d_in, const int* in_sizes, int n_in,
                              void* d_out, int out_size) {
    // metadata order: x, qw, qb, kw, kb, mw, mb, scaling, g1w, g1b, g2w, g2b
    const float* x   = (const float*)d_in[0];
    const float* mw  = (const float*)d_in[5];
    const float* mb  = (const float*)d_in[6];
    const float* g1w = (const float*)d_in[8];
    const float* g1b = (const float*)d_in[9];
    const float* g2w = (const float*)d_in[10];
    const float* g2b = (const float*)d_in[11];
    float* out = (float*)d_out;

    // 1,048,576 px -> 524,288 horizontal pairs -> 2048 blocks x 256 threads
    fused_graphaug_kernel<<<2048, 256>>>(x, mw, mb, g1w, g1b, g2w, g2b, out);
}

// round 4
// speedup vs baseline: 1.3156x; 1.3156x over previous
#include <cuda_runtime.h>

#define C16  16
#define GH32 32
#define W512 512
#define HW   (512 * 512)

// Packed f32x2 FMA (Blackwell sm_103a) — 2 fp32 FMAs per instruction.
__device__ __forceinline__ float2 ffma2(float2 a, float2 b, float2 c) {
    float2 d;
    asm("fma.rn.f32x2 %0, %1, %2, %3;"
        : "=l"(reinterpret_cast<unsigned long long&>(d))
        : "l"(reinterpret_cast<unsigned long long&>(a)),
          "l"(reinterpret_cast<unsigned long long&>(b)),
          "l"(reinterpret_cast<unsigned long long&>(c)));
    return d;
}
__device__ __forceinline__ float2 dup2(float v) { return make_float2(v, v); }

// Identity: softmax over 8 identical affinities = 1/8 each, so
//   s      = mean of 8 rolls of x
//   agg    = mw @ s + mb
//   hidden = relu(W1 @ x + W2 @ s + b1'),  W2 = g1w[:,16:] @ mw,
//            b1' = g1b + g1w[:,16:] @ mb
//   out    = agg * sigmoid(g2w @ hidden + g2b)
//
// f32x2 lanes = OUTPUT-channel pairs (j,j+1) per pixel (not pixel pairs):
// weights load at full density (LDS.128 = 4 distinct weights = 4 FFMA2),
// activations are duplicated via cheap register movs. This halves the
// weight-LDS traffic that bound rounds 1-3 while keeping regs under 128.
__global__ __launch_bounds__(256, 2) void fused_graphaug_kernel(
    const float* __restrict__ x,
    const float* __restrict__ mw,  const float* __restrict__ mb,
    const float* __restrict__ g1w, const float* __restrict__ g1b,
    const float* __restrict__ g2w, const float* __restrict__ g2b,
    float* __restrict__ out)
{
    // Natural (non-duplicated) weight layouts, pairs along the OUTPUT dim.
    __shared__ __align__(16) float sW1[C16 * GH32];     // [c][j]   = g1w[j][c]
    __shared__ __align__(16) float sW2[C16 * GH32];     // [c][j]   = (g1w[:,16:] @ mw)[j][c]
    __shared__ __align__(16) float sG2[8 * GH32 * 2];   // [gp][j][e] = g2w[2gp+e][j]
    __shared__ __align__(16) float sMW[C16 * C16];      // [c][d]   = mw[d][c]
    __shared__ __align__(16) float sB1[GH32];           // folded bias, pairs along j
    __shared__ __align__(16) float sGB[C16];            // g2b, pairs along g
    __shared__ __align__(16) float sMB[C16];            // mb, pairs along d

    const int t = threadIdx.x;

    // ---- Stage weights ----
    for (int i = t; i < C16 * GH32; i += 256) {
        int c = i >> 5, j = i & 31;
        sW1[i] = g1w[j * (2 * C16) + c];
        float acc = 0.f;
        #pragma unroll
        for (int k = 0; k < C16; k++)
            acc += g1w[j * (2 * C16) + C16 + k] * mw[k * C16 + c];
        sW2[i] = acc;
    }
    for (int i = t; i < 8 * GH32 * 2; i += 256) {
        int gp = i >> 6, r = i & 63, j = r >> 1, e = r & 1;
        sG2[i] = g2w[(2 * gp + e) * GH32 + j];
    }
    for (int i = t; i < C16 * C16; i += 256) {
        int c = i >> 4, d = i & 15;
        sMW[i] = mw[d * C16 + c];
    }
    if (t < GH32) {
        float acc = g1b[t];
        #pragma unroll
        for (int k = 0; k < C16; k++)
            acc += g1w[t * (2 * C16) + C16 + k] * mb[k];
        sB1[t] = acc;
    }
    if (t >= 32 && t < 32 + C16) sMB[t - 32] = mb[t - 32];
    if (t >= 64 && t < 64 + C16) sGB[t - 64] = g2b[t - 64];
    __syncthreads();

    // ---- Pixel-pair indexing (2 horizontally-adjacent pixels per thread) ----
    const int tidg = blockIdx.x * 256 + t;
    const int p0   = tidg * 2;
    const int w0   = p0 & (W512 - 1);            // even column
    const int h    = (p0 >> 9) & (W512 - 1);
    const int b    = p0 >> 18;

    const float* xb    = x + (size_t)b * C16 * HW;
    const int    center = h * W512 + w0;

    constexpr int DY[8] = {-4, -4, -4, -3, -2, 2, 3, 4};
    constexpr int DX[8] = {-4, -1,  2,  4, -3, 3, -2, 4};
    int roff[8], cb[8];
    #pragma unroll
    for (int i = 0; i < 8; i++) {
        roff[i] = ((h - DY[i]) & (W512 - 1)) * W512;
        cb[i]   = (w0 - DX[i]) & (W512 - 1);
    }

    // ---- s = mean of 8 rolls, per channel, SCALAR per pixel ----
    float sv0[C16], sv1[C16];                    // px0 = (h,w0), px1 = (h,w0+1)
    #pragma unroll
    for (int c = 0; c < C16; c++) {
        const float* xp = xb + c * HW;
        float a0 = 0.f, a1 = 0.f;
        #pragma unroll
        for (int i = 0; i < 8; i++) {
            if ((DX[i] & 1) == 0) {
                float2 v = *reinterpret_cast<const float2*>(xp + roff[i] + cb[i]);
                a0 += v.x; a1 += v.y;
            } else {
                a0 += __ldg(xp + roff[i] + cb[i]);
                a1 += __ldg(xp + roff[i] + ((cb[i] + 1) & (W512 - 1)));
            }
        }
        sv0[c] = a0 * 0.125f;
        sv1[c] = a1 * 0.125f;
    }

    // ---- gate accumulators: gacc[gp][px] packs outputs (2gp, 2gp+1) ----
    float2 gacc[8][2];
    #pragma unroll
    for (int gp = 0; gp < 8; gp++) {
        float2 gb = *reinterpret_cast<const float2*>(&sGB[2 * gp]);
        gacc[gp][0] = gb; gacc[gp][1] = gb;
    }

    // ---- hidden in 4 chunks of 8 units (4 j-pairs) ----
    #pragma unroll
    for (int jt = 0; jt < 4; jt++) {
        const int j0 = jt * 8;                   // first unit of chunk
        float2 hreg[4][2];                       // [jp_local][px], packs (j, j+1)
        #pragma unroll
        for (int jl = 0; jl < 4; jl++) {
            float2 bv = *reinterpret_cast<const float2*>(&sB1[j0 + 2 * jl]);
            hreg[jl][0] = bv; hreg[jl][1] = bv;
        }
        // W1 @ x : weight LDS.128 = 4 distinct weights -> 4 FFMA2 per px
        #pragma unroll
        for (int c = 0; c < C16; c++) {
            float2 xc = *reinterpret_cast<const float2*>(xb + c * HW + center);
            float2 xd0 = dup2(xc.x), xd1 = dup2(xc.y);
            float4 wa = *reinterpret_cast<const float4*>(&sW1[c * GH32 + j0]);
            float4 wb = *reinterpret_cast<const float4*>(&sW1[c * GH32 + j0 + 4]);
            hreg[0][0] = ffma2(make_float2(wa.x, wa.y), xd0, hreg[0][0]);
            hreg[0][1] = ffma2(make_float2(wa.x, wa.y), xd1, hreg[0][1]);
            hreg[1][0] = ffma2(make_float2(wa.z, wa.w), xd0, hreg[1][0]);
            hreg[1][1] = ffma2(make_float2(wa.z, wa.w), xd1, hreg[1][1]);
            hreg[2][0] = ffma2(make_float2(wb.x, wb.y), xd0, hreg[2][0]);
            hreg[2][1] = ffma2(make_float2(wb.x, wb.y), xd1, hreg[2][1]);
            hreg[3][0] = ffma2(make_float2(wb.z, wb.w), xd0, hreg[3][0]);
            hreg[3][1] = ffma2(make_float2(wb.z, wb.w), xd1, hreg[3][1]);
        }
        // W2 @ s
        #pragma unroll
        for (int c = 0; c < C16; c++) {
            float2 sd0 = dup2(sv0[c]), sd1 = dup2(sv1[c]);
            float4 wa = *reinterpret_cast<const float4*>(&sW2[c * GH32 + j0]);
            float4 wb = *reinterpret_cast<const float4*>(&sW2[c * GH32 + j0 + 4]);
            hreg[0][0] = ffma2(make_float2(wa.x, wa.y), sd0, hreg[0][0]);
            hreg[0][1] = ffma2(make_float2(wa.x, wa.y), sd1, hreg[0][1]);
            hreg[1][0] = ffma2(make_float2(wa.z, wa.w), sd0, hreg[1][0]);
            hreg[1][1] = ffma2(make_float2(wa.z, wa.w), sd1, hreg[1][1]);
            hreg[2][0] = ffma2(make_float2(wb.x, wb.y), sd0, hreg[2][0]);
            hreg[2][1] = ffma2(make_float2(wb.x, wb.y), sd1, hreg[2][1]);
            hreg[3][0] = ffma2(make_float2(wb.z, wb.w), sd0, hreg[3][0]);
            hreg[3][1] = ffma2(make_float2(wb.z, wb.w), sd1, hreg[3][1]);
        }
        // relu
        #pragma unroll
        for (int jl = 0; jl < 4; jl++) {
            hreg[jl][0].x = fmaxf(hreg[jl][0].x, 0.f);
            hreg[jl][0].y = fmaxf(hreg[jl][0].y, 0.f);
            hreg[jl][1].x = fmaxf(hreg[jl][1].x, 0.f);
            hreg[jl][1].y = fmaxf(hreg[jl][1].y, 0.f);
        }
        // gate accumulation: for each j-pair, one LDS.128 per gp covers
        // (w[j,2gp], w[j,2gp+1], w[j+1,2gp], w[j+1,2gp+1])
        #pragma unroll
        for (int jl = 0; jl < 4; jl++) {
            const int jg = j0 + 2 * jl;          // global j (even)
            float2 ha0 = dup2(hreg[jl][0].x), hb0 = dup2(hreg[jl][0].y);
            float2 ha1 = dup2(hreg[jl][1].x), hb1 = dup2(hreg[jl][1].y);
            #pragma unroll
            for (int gp = 0; gp < 8; gp++) {
                float4 wq = *reinterpret_cast<const float4*>(&sG2[gp * 64 + jg * 2]);
                gacc[gp][0] = ffma2(make_float2(wq.x, wq.y), ha0, gacc[gp][0]);
                gacc[gp][0] = ffma2(make_float2(wq.z, wq.w), hb0, gacc[gp][0]);
                gacc[gp][1] = ffma2(make_float2(wq.x, wq.y), ha1, gacc[gp][1]);
                gacc[gp][1] = ffma2(make_float2(wq.z, wq.w), hb1, gacc[gp][1]);
            }
        }
    }

    // ---- agg = mw @ s + mb : agg[dp][px] packs outputs (2dp, 2dp+1) ----
    float2 agg[8][2];
    #pragma unroll
    for (int dp = 0; dp < 8; dp++) {
        float2 mv = *reinterpret_cast<const float2*>(&sMB[2 * dp]);
        agg[dp][0] = mv; agg[dp][1] = mv;
    }
    #pragma unroll
    for (int c = 0; c < C16; c++) {
        float2 sd0 = dup2(sv0[c]), sd1 = dup2(sv1[c]);
        #pragma unroll
        for (int dp = 0; dp < 8; dp += 2) {
            float4 wq = *reinterpret_cast<const float4*>(&sMW[c * C16 + dp * 2]);
            agg[dp][0]     = ffma2(make_float2(wq.x, wq.y), sd0, agg[dp][0]);
            agg[dp][1]     = ffma2(make_float2(wq.x, wq.y), sd1, agg[dp][1]);
            agg[dp + 1][0] = ffma2(make_float2(wq.z, wq.w), sd0, agg[dp + 1][0]);
            agg[dp + 1][1] = ffma2(make_float2(wq.z, wq.w), sd1, agg[dp + 1][1]);
        }
    }

    // ---- epilogue: out = agg * sigmoid(gacc), repacked to pixel-major ----
    float* ob = out + (size_t)b * C16 * HW + center;
    #pragma unroll
    for (int dp = 0; dp < 8; dp++) {
        const int d0 = 2 * dp;
        float g00 = 1.f / (1.f + __expf(-gacc[dp][0].x));  // d0 @ px0
        float g01 = 1.f / (1.f + __expf(-gacc[dp][1].x));  // d0 @ px1
        float g10 = 1.f / (1.f + __expf(-gacc[dp][0].y));  // d1 @ px0
        float g11 = 1.f / (1.f + __expf(-gacc[dp][1].y));  // d1 @ px1
        *reinterpret_cast<float2*>(ob + (size_t)d0 * HW) =
            make_float2(agg[dp][0].x * g00, agg[dp][1].x * g01);
        *reinterpret_cast<float2*>(ob + (size_t)(d0 + 1) * HW) =
            make_float2(agg[dp][0].y * g10, agg[dp][1].y * g11);
    }
}

extern "C" void kernel_launch(void* const* d_in, const int* in_sizes, int n_in,
                              void* d_out, int out_size) {
    // metadata order: x, qw, qb, kw, kb, mw, mb, scaling, g1w, g1b, g2w, g2b
    const float* x   = (const float*)d_in[0];
    const float* mw  = (const float*)d_in[5];
    const float* mb  = (const float*)d_in[6];
    const float* g1w = (const float*)d_in[8];
    const float* g1b = (const float*)d_in[9];
    const float* g2w = (const float*)d_in[10];
    const float* g2b = (const float*)d_in[11];
    float* out = (float*)d_out;

    // 1,048,576 px -> 524,288 horizontal pairs -> 2048 blocks x 256 threads
    fused_graphaug_kernel<<<2048, 256>>>(x, mw, mb, g1w, g1b, g2w, g2b, out);
}

// round 5
// speedup vs baseline: 1.7355x; 1.3192x over previous
#include <cuda_runtime.h>

#define C16  16
#define GH32 32
#define W512 512
#define HW   (512 * 512)

// Constant-bank weight layout (floats). W1/W2/G2 + biases live here: LDC uses
// the dedicated constant port (2 cyc/SM per instr), NOT the L1tex pipe that
// bound rounds 1-4 (broadcast LDS.128 writes back 512 B -> 4 cyc/SM each).
#define OFF_W1 0        // [c][j]      16*32
#define OFF_W2 512      // [c][j]      16*32  (= g1w[:,16:] @ mw, folded)
#define OFF_G2 1024     // [gp][j][e]  8*32*2 (= g2w[2gp+e][j])
#define OFF_B1 1536     // 32          (= g1b + g1w[:,16:] @ mb)
#define OFF_GB 1568     // 16          (g2b)
#define OFF_MB 1584     // 16          (mb)
#define NWC    1600

__constant__ __align__(16) float cwts[NWC];
__device__   __align__(16) float g_wbuf[NWC];

// Packed f32x2 FMA (Blackwell sm_103a) — 2 fp32 FMAs per instruction.
__device__ __forceinline__ float2 ffma2(float2 a, float2 b, float2 c) {
    float2 d;
    asm("fma.rn.f32x2 %0, %1, %2, %3;"
        : "=l"(reinterpret_cast<unsigned long long&>(d))
        : "l"(reinterpret_cast<unsigned long long&>(a)),
          "l"(reinterpret_cast<unsigned long long&>(b)),
          "l"(reinterpret_cast<unsigned long long&>(c)));
    return d;
}
__device__ __forceinline__ float2 dup2(float v) { return make_float2(v, v); }
__device__ __forceinline__ float4 ldc4(int idx) {
    return *reinterpret_cast<const float4*>(&cwts[idx]);
}
__device__ __forceinline__ float2 ldc2(int idx) {
    return *reinterpret_cast<const float2*>(&cwts[idx]);
}

// ---- prep: fold weights into constant-bank staging buffer ----
__global__ void prep_weights(const float* __restrict__ mw,  const float* __restrict__ mb,
                             const float* __restrict__ g1w, const float* __restrict__ g1b,
                             const float* __restrict__ g2w, const float* __restrict__ g2b)
{
    const int t = threadIdx.x;
    for (int i = t; i < C16 * GH32; i += 256) {
        int c = i >> 5, j = i & 31;
        g_wbuf[OFF_W1 + i] = g1w[j * (2 * C16) + c];
        float acc = 0.f;
        #pragma unroll
        for (int k = 0; k < C16; k++)
            acc += g1w[j * (2 * C16) + C16 + k] * mw[k * C16 + c];
        g_wbuf[OFF_W2 + i] = acc;
    }
    for (int i = t; i < 8 * GH32 * 2; i += 256) {
        int gp = i >> 6, r = i & 63, j = r >> 1, e = r & 1;
        g_wbuf[OFF_G2 + i] = g2w[(2 * gp + e) * GH32 + j];
    }
    if (t < GH32) {
        float acc = g1b[t];
        #pragma unroll
        for (int k = 0; k < C16; k++)
            acc += g1w[t * (2 * C16) + C16 + k] * mb[k];
        g_wbuf[OFF_B1 + t] = acc;
    }
    if (t >= 32 && t < 32 + C16) g_wbuf[OFF_MB + t - 32] = mb[t - 32];
    if (t >= 64 && t < 64 + C16) g_wbuf[OFF_GB + t - 64] = g2b[t - 64];
}

// Identity: softmax over 8 identical affinities = 1/8 each, so
//   s      = mean of 8 rolls of x
//   agg    = mw @ s + mb
//   hidden = relu(W1 @ x + W2 @ s + b1')
//   out    = agg * sigmoid(g2w @ hidden + g2b)
// f32x2 lanes pack OUTPUT-channel pairs; one thread = 2 adjacent pixels.
// W1/W2/G2 weights come from the constant port; MW stays in smem so the
// const port and L1 pipe are load-balanced (~42us each by model).
__global__ __launch_bounds__(256, 2) void fused_graphaug_kernel(
    const float* __restrict__ x,
    const float* __restrict__ mw,
    float* __restrict__ out)
{
    __shared__ __align__(16) float sMW[C16 * C16];   // [c][d] = mw[d][c]
    const int t = threadIdx.x;
    if (t < 256) {
        int c = t >> 4, d = t & 15;
        sMW[t] = mw[d * C16 + c];
    }
    __syncthreads();

    // ---- Pixel-pair indexing ----
    const int tidg = blockIdx.x * 256 + t;
    const int p0   = tidg * 2;
    const int w0   = p0 & (W512 - 1);            // even column
    const int h    = (p0 >> 9) & (W512 - 1);
    const int b    = p0 >> 18;

    const float* xb    = x + (size_t)b * C16 * HW;
    const int    center = h * W512 + w0;

    constexpr int DY[8] = {-4, -4, -4, -3, -2, 2, 3, 4};
    constexpr int DX[8] = {-4, -1,  2,  4, -3, 3, -2, 4};
    int roff[8], cb[8];
    #pragma unroll
    for (int i = 0; i < 8; i++) {
        roff[i] = ((h - DY[i]) & (W512 - 1)) * W512;
        cb[i]   = (w0 - DX[i]) & (W512 - 1);
    }

    // ---- s = mean of 8 rolls, per channel, scalar per pixel ----
    float sv0[C16], sv1[C16];
    #pragma unroll
    for (int c = 0; c < C16; c++) {
        const float* xp = xb + c * HW;
        float a0 = 0.f, a1 = 0.f;
        #pragma unroll
        for (int i = 0; i < 8; i++) {
            if ((DX[i] & 1) == 0) {
                float2 v = *reinterpret_cast<const float2*>(xp + roff[i] + cb[i]);
                a0 += v.x; a1 += v.y;
            } else {
                a0 += __ldg(xp + roff[i] + cb[i]);
                a1 += __ldg(xp + roff[i] + ((cb[i] + 1) & (W512 - 1)));
            }
        }
        sv0[c] = a0 * 0.125f;
        sv1[c] = a1 * 0.125f;
    }

    // ---- gate accumulators: gacc[gp][px] packs outputs (2gp, 2gp+1) ----
    float2 gacc[8][2];
    #pragma unroll
    for (int gp = 0; gp < 8; gp++) {
        float2 gb = ldc2(OFF_GB + 2 * gp);
        gacc[gp][0] = gb; gacc[gp][1] = gb;
    }

    // ---- hidden in 4 chunks of 8 units ----
    #pragma unroll
    for (int jt = 0; jt < 4; jt++) {
        const int j0 = jt * 8;
        float2 hreg[4][2];
        #pragma unroll
        for (int jl = 0; jl < 4; jl++) {
            float2 bv = ldc2(OFF_B1 + j0 + 2 * jl);
            hreg[jl][0] = bv; hreg[jl][1] = bv;
        }
        // W1 @ x (constant port)
        #pragma unroll
        for (int c = 0; c < C16; c++) {
            float2 xc = *reinterpret_cast<const float2*>(xb + c * HW + center);
            float2 xd0 = dup2(xc.x), xd1 = dup2(xc.y);
            float4 wa = ldc4(OFF_W1 + c * GH32 + j0);
            float4 wb = ldc4(OFF_W1 + c * GH32 + j0 + 4);
            hreg[0][0] = ffma2(make_float2(wa.x, wa.y), xd0, hreg[0][0]);
            hreg[0][1] = ffma2(make_float2(wa.x, wa.y), xd1, hreg[0][1]);
            hreg[1][0] = ffma2(make_float2(wa.z, wa.w), xd0, hreg[1][0]);
            hreg[1][1] = ffma2(make_float2(wa.z, wa.w), xd1, hreg[1][1]);
            hreg[2][0] = ffma2(make_float2(wb.x, wb.y), xd0, hreg[2][0]);
            hreg[2][1] = ffma2(make_float2(wb.x, wb.y), xd1, hreg[2][1]);
            hreg[3][0] = ffma2(make_float2(wb.z, wb.w), xd0, hreg[3][0]);
            hreg[3][1] = ffma2(make_float2(wb.z, wb.w), xd1, hreg[3][1]);
        }
        // W2 @ s (constant port)
        #pragma unroll
        for (int c = 0; c < C16; c++) {
            float2 sd0 = dup2(sv0[c]), sd1 = dup2(sv1[c]);
            float4 wa = ldc4(OFF_W2 + c * GH32 + j0);
            float4 wb = ldc4(OFF_W2 + c * GH32 + j0 + 4);
            hreg[0][0] = ffma2(make_float2(wa.x, wa.y), sd0, hreg[0][0]);
            hreg[0][1] = ffma2(make_float2(wa.x, wa.y), sd1, hreg[0][1]);
            hreg[1][0] = ffma2(make_float2(wa.z, wa.w), sd0, hreg[1][0]);
            hreg[1][1] = ffma2(make_float2(wa.z, wa.w), sd1, hreg[1][1]);
            hreg[2][0] = ffma2(make_float2(wb.x, wb.y), sd0, hreg[2][0]);
            hreg[2][1] = ffma2(make_float2(wb.x, wb.y), sd1, hreg[2][1]);
            hreg[3][0] = ffma2(make_float2(wb.z, wb.w), sd0, hreg[3][0]);
            hreg[3][1] = ffma2(make_float2(wb.z, wb.w), sd1, hreg[3][1]);
        }
        // relu
        #pragma unroll
        for (int jl = 0; jl < 4; jl++) {
            hreg[jl][0].x = fmaxf(hreg[jl][0].x, 0.f);
            hreg[jl][0].y = fmaxf(hreg[jl][0].y, 0.f);
            hreg[jl][1].x = fmaxf(hreg[jl][1].x, 0.f);
            hreg[jl][1].y = fmaxf(hreg[jl][1].y, 0.f);
        }
        // gate accumulation (constant port)
        #pragma unroll
        for (int jl = 0; jl < 4; jl++) {
            const int jg = j0 + 2 * jl;
            float2 ha0 = dup2(hreg[jl][0].x), hb0 = dup2(hreg[jl][0].y);
            float2 ha1 = dup2(hreg[jl][1].x), hb1 = dup2(hreg[jl][1].y);
            #pragma unroll
            for (int gp = 0; gp < 8; gp++) {
                float4 wq = ldc4(OFF_G2 + gp * 64 + jg * 2);
                gacc[gp][0] = ffma2(make_float2(wq.x, wq.y), ha0, gacc[gp][0]);
                gacc[gp][0] = ffma2(make_float2(wq.z, wq.w), hb0, gacc[gp][0]);
                gacc[gp][1] = ffma2(make_float2(wq.x, wq.y), ha1, gacc[gp][1]);
                gacc[gp][1] = ffma2(make_float2(wq.z, wq.w), hb1, gacc[gp][1]);
            }
        }
    }

    // ---- agg = mw @ s + mb (MW from smem: balances L1 vs const port) ----
    float2 agg[8][2];
    #pragma unroll
    for (int dp = 0; dp < 8; dp++) {
        float2 mv = ldc2(OFF_MB + 2 * dp);
        agg[dp][0] = mv; agg[dp][1] = mv;
    }
    #pragma unroll
    for (int c = 0; c < C16; c++) {
        float2 sd0 = dup2(sv0[c]), sd1 = dup2(sv1[c]);
        #pragma unroll
        for (int dp = 0; dp < 8; dp += 2) {
            float4 wq = *reinterpret_cast<const float4*>(&sMW[c * C16 + dp * 2]);
            agg[dp][0]     = ffma2(make_float2(wq.x, wq.y), sd0, agg[dp][0]);
            agg[dp][1]     = ffma2(make_float2(wq.x, wq.y), sd1, agg[dp][1]);
            agg[dp + 1][0] = ffma2(make_float2(wq.z, wq.w), sd0, agg[dp + 1][0]);
            agg[dp + 1][1] = ffma2(make_float2(wq.z, wq.w), sd1, agg[dp + 1][1]);
        }
    }

    // ---- epilogue: out = agg * sigmoid(gacc) ----
    float* ob = out + (size_t)b * C16 * HW + center;
    #pragma unroll
    for (int dp = 0; dp < 8; dp++) {
        const int d0 = 2 * dp;
        float g00 = 1.f / (1.f + __expf(-gacc[dp][0].x));
        float g01 = 1.f / (1.f + __expf(-gacc[dp][1].x));
        float g10 = 1.f / (1.f + __expf(-gacc[dp][0].y));
        float g11 = 1.f / (1.f + __expf(-gacc[dp][1].y));
        *reinterpret_cast<float2*>(ob + (size_t)d0 * HW) =
            make_float2(agg[dp][0].x * g00, agg[dp][1].x * g01);
        *reinterpret_cast<float2*>(ob + (size_t)(d0 + 1) * HW) =
            make_float2(agg[dp][0].y * g10, agg[dp][1].y * g11);
    }
}

extern "C" void kernel_launch(void* const* d_in, const int* in_sizes, int n_in,
                              void* d_out, int out_size) {
    // metadata order: x, qw, qb, kw, kb, mw, mb, scaling, g1w, g1b, g2w, g2b
    const float* x   = (const float*)d_in[0];
    const float* mw  = (const float*)d_in[5];
    const float* mb  = (const float*)d_in[6];
    const float* g1w = (const float*)d_in[8];
    const float* g1b = (const float*)d_in[9];
    const float* g2w = (const float*)d_in[10];
    const float* g2b = (const float*)d_in[11];
    float* out = (float*)d_out;

    prep_weights<<<1, 256>>>(mw, mb, g1w, g1b, g2w, g2b);

    void* wsrc = nullptr;
    cudaGetSymbolAddress(&wsrc, g_wbuf);
    cudaMemcpyToSymbolAsync(cwts, wsrc, NWC * sizeof(float), 0,
                            cudaMemcpyDeviceToDevice, 0);

    // 1,048,576 px -> 524,288 horizontal pairs -> 2048 blocks x 256 threads
    fused_graphaug_kernel<<<2048, 256>>>(x, mw, out);
}